// round 15
// baseline (speedup 1.0000x reference)
#include <cuda_runtime.h>
#include <math.h>
#include <cstdint>

#define T_STEPS 512
#define BATCH   128
#define IN_DIM  544
#define HID     512
#define G4H     2048
#define NACT    19
#define NCTA    256     // CTA = (batch-quarter, unit-group of 8); 2 CTAs per SM
#define TPB     128     // 4 warps: warp = (m-tile 0..1, n-pair 0..1)
#define NU      8       // units per CTA (32 gate rows)

// LSTM SMEM: three (A 32x132 + B 32x132) circular buffers
#define SM_AB    16896                        // B offset inside a buffer
#define SM_BUF   33792                        // buffer stride
#define SM_TOTAL (3 * SM_BUF)                 // 101376  -> 2 CTAs/SM
#define DS_STR   36

// pre-GEMM (mma) SMEM
#define PM_STR   140
#define PM_A     0
#define PM_B     (64 * PM_STR * 4)
#define PM_BIAS  (PM_B + 128 * PM_STR * 4)
#define PM_TOTAL (PM_BIAS + 512)

// ---------------- scratch ----------------------------------------------------
__device__ float g_pre0[(size_t)T_STEPS * G4H * BATCH];     // [t][n][b]
__device__ float g_hidden[(size_t)T_STEPS * BATCH * HID];
__device__ float g_h0[2][BATCH][HID];                       // tf32-rounded h
__device__ float g_h1[2][BATCH][HID];
__device__ float g_wt0[G4H * HID];                          // tf32-rounded weights
__device__ float g_wt1i[G4H * HID];
__device__ float g_wt1h[G4H * HID];
__device__ unsigned int g_bar_count;
__device__ unsigned int g_bar_release;

// ---------------- helpers ----------------------------------------------------
__device__ __forceinline__ uint32_t smem_u32(const void* p) {
    uint32_t a;
    asm("{ .reg .u64 t; cvta.to.shared.u64 t, %1; cvt.u32.u64 %0, t; }" : "=r"(a) : "l"(p));
    return a;
}
__device__ __forceinline__ float tf32r(float x) {
    uint32_t o; asm("cvt.rna.tf32.f32 %0, %1;" : "=r"(o) : "f"(x));
    return __uint_as_float(o);
}
__device__ __forceinline__ void ldsm4(uint32_t* r, uint32_t addr) {
    asm volatile("ldmatrix.sync.aligned.m8n8.x4.shared.b16 {%0,%1,%2,%3}, [%4];"
                 : "=r"(r[0]), "=r"(r[1]), "=r"(r[2]), "=r"(r[3]) : "r"(addr));
}
__device__ __forceinline__ void mma_tf32(float* d, const uint32_t* a, const uint32_t* b) {
    asm volatile("mma.sync.aligned.m16n8k8.row.col.f32.tf32.tf32.f32 "
                 "{%0,%1,%2,%3}, {%4,%5,%6,%7}, {%8,%9}, {%0,%1,%2,%3};"
                 : "+f"(d[0]), "+f"(d[1]), "+f"(d[2]), "+f"(d[3])
                 : "r"(a[0]), "r"(a[1]), "r"(a[2]), "r"(a[3]), "r"(b[0]), "r"(b[1]));
}
__device__ __forceinline__ void cp16cg(uint32_t d, const void* s) {
    asm volatile("cp.async.cg.shared.global [%0], [%1], 16;" :: "r"(d), "l"(s));
}
__device__ __forceinline__ void cp16ca(uint32_t d, const void* s) {
    asm volatile("cp.async.ca.shared.global [%0], [%1], 16;" :: "r"(d), "l"(s));
}
#define CP_COMMIT() asm volatile("cp.async.commit_group;" ::: "memory")
#define CP_WAIT1()  asm volatile("cp.async.wait_group 1;" ::: "memory")
__device__ __forceinline__ float sigmoidf_(float x) { return 1.f / (1.f + expf(-x)); }

// ---------------- init / weight-round kernels --------------------------------
__global__ void init_kernel(const float* __restrict__ h0) {
    if (blockIdx.x == 0 && threadIdx.x == 0) { g_bar_count = 0u; g_bar_release = 0u; }
    const int n = BATCH * HID;
    for (int i = blockIdx.x * blockDim.x + threadIdx.x; i < n; i += gridDim.x * blockDim.x) {
        (&g_h0[0][0][0])[i] = tf32r(h0[i]);
        (&g_h1[0][0][0])[i] = tf32r(h0[n + i]);
    }
}

__global__ void wt_kernel(const float* __restrict__ W0, const float* __restrict__ W1i,
                          const float* __restrict__ W1h) {
    const int n = G4H * HID;
    for (int i = blockIdx.x * blockDim.x + threadIdx.x; i < n; i += gridDim.x * blockDim.x) {
        g_wt0[i]  = tf32r(W0[i]);
        g_wt1i[i] = tf32r(W1i[i]);
        g_wt1h[i] = tf32r(W1h[i]);
    }
}

// ---------------- pre-GEMM via tf32 mma (unchanged) ---------------------------
__global__ void __launch_bounds__(256)
pre_mma_kernel(const float* __restrict__ X, const float* __restrict__ W,
               const float* __restrict__ bA, const float* __restrict__ bB)
{
    extern __shared__ char sm[];
    float* bias = (float*)(sm + PM_BIAS);
    float* D_s  = (float*)sm;

    const int tid  = threadIdx.x;
    const int w    = tid >> 5;
    const int lane = tid & 31;
    const int n0   = blockIdx.x * 128;
    const int row0 = blockIdx.y * 64;
    const int tt   = blockIdx.y >> 1;
    const int b0   = (blockIdx.y & 1) * 64;
    const int mt   = w >> 1;
    const int nh   = w & 1;

    if (tid < 128) bias[tid] = bA[n0 + tid] + bB[n0 + tid];

    const uint32_t sb = smem_u32(sm);
    const int st = lane >> 3;
    const uint32_t aA = sb + PM_A + (mt * 16 + (st & 1) * 8 + (lane & 7)) * 560 + (st >> 1) * 16;
    const uint32_t bBq = sb + PM_B + (nh * 64 + (st >> 1) * 8 + (lane & 7)) * 560 + (st & 1) * 16;

    float acc[32];
#pragma unroll
    for (int i = 0; i < 32; i++) acc[i] = 0.f;

    for (int kc = 0; kc < 4; kc++) {
        __syncthreads();
        {
            const int r = tid >> 2, q = tid & 3;
#pragma unroll
            for (int j = 0; j < 9; j++) {
                int c4 = j * 4 + q;
                if (c4 < 34) {
                    float4 v = __ldg((const float4*)&X[(size_t)(row0 + r) * IN_DIM + kc * 136 + c4 * 4]);
                    v.x = tf32r(v.x); v.y = tf32r(v.y); v.z = tf32r(v.z); v.w = tf32r(v.w);
                    *(float4*)(sm + PM_A + r * 560 + c4 * 16) = v;
                }
            }
        }
        {
            const int r = tid >> 1, q = tid & 1;
#pragma unroll
            for (int j = 0; j < 17; j++) {
                int c4 = j * 2 + q;
                float4 v = __ldg((const float4*)&W[(size_t)(n0 + r) * IN_DIM + kc * 136 + c4 * 4]);
                v.x = tf32r(v.x); v.y = tf32r(v.y); v.z = tf32r(v.z); v.w = tf32r(v.w);
                *(float4*)(sm + PM_B + r * 560 + c4 * 16) = v;
            }
        }
        __syncthreads();
#pragma unroll
        for (int ks = 0; ks < 17; ks++) {
            uint32_t af[4];
            ldsm4(af, aA + ks * 32);
#pragma unroll
            for (int nb = 0; nb < 4; nb++) {
                uint32_t bf[4];
                ldsm4(bf, bBq + nb * 16 * 560 + ks * 32);
                mma_tf32(acc + nb * 8 + 0, af, bf + 0);
                mma_tf32(acc + nb * 8 + 4, af, bf + 2);
            }
        }
    }

    __syncthreads();
    {
        const int r = lane >> 2, c2 = (lane & 3) * 2;
#pragma unroll
        for (int nb = 0; nb < 4; nb++) {
            const int nbase = nh * 64 + nb * 16;
            D_s[(nbase + c2 + 0) * 68 + mt * 16 + r]     = acc[nb * 8 + 0];
            D_s[(nbase + c2 + 1) * 68 + mt * 16 + r]     = acc[nb * 8 + 1];
            D_s[(nbase + c2 + 0) * 68 + mt * 16 + r + 8] = acc[nb * 8 + 2];
            D_s[(nbase + c2 + 1) * 68 + mt * 16 + r + 8] = acc[nb * 8 + 3];
            D_s[(nbase + 8 + c2 + 0) * 68 + mt * 16 + r]     = acc[nb * 8 + 4];
            D_s[(nbase + 8 + c2 + 1) * 68 + mt * 16 + r]     = acc[nb * 8 + 5];
            D_s[(nbase + 8 + c2 + 0) * 68 + mt * 16 + r + 8] = acc[nb * 8 + 6];
            D_s[(nbase + 8 + c2 + 1) * 68 + mt * 16 + r + 8] = acc[nb * 8 + 7];
        }
    }
    __syncthreads();
    {
        const int n = tid >> 1, mh = tid & 1;
        const float bs = bias[n];
        float* dst = &g_pre0[((size_t)tt * G4H + n0 + n) * BATCH + b0 + mh * 32];
        const float* src = &D_s[n * 68 + mh * 32];
#pragma unroll
        for (int s = 0; s < 8; s++) {
            float4 v = ((const float4*)src)[s];
            ((float4*)dst)[s] = make_float4(v.x + bs, v.y + bs, v.z + bs, v.w + bs);
        }
    }
}

// ---------------- persistent tensor (mma.sync + cp.async) LSTM ----------------
__device__ __forceinline__ void grid_bar(unsigned int phase) {
    __threadfence();
    __syncthreads();
    if (threadIdx.x == 0) {
        unsigned int arrived = atomicAdd(&g_bar_count, 1u) + 1u;
        if (arrived == (unsigned)NCTA * phase) {
            atomicExch(&g_bar_release, phase);
        } else {
            while (*(volatile unsigned int*)&g_bar_release < phase) { __nanosleep(64); }
        }
    }
    __syncthreads();
}

// stage one chunk into buffer: A 32 rows (batch quarter), B 32 gate rows
__device__ __forceinline__ void stage_async(uint32_t sbuf,
                                            const float* __restrict__ srcA,
                                            const float* __restrict__ srcB,
                                            int kc, int B0, int u0, int tid)
{
#pragma unroll
    for (int it = 0; it < 8; it++) {
        const int idx = it * TPB + tid;
        const int m  = idx >> 5;
        const int kq = (idx & 31) << 2;
        cp16cg(sbuf + m * 528 + kq * 4, &srcA[(B0 + m) * HID + kc * 128 + kq]);
    }
#pragma unroll
    for (int it = 0; it < 8; it++) {
        const int idx = it * TPB + tid;
        const int r  = idx >> 5;
        const int kq = (idx & 31) << 2;
        const int grow = (r >> 3) * HID + u0 + (r & 7);
        cp16ca(sbuf + SM_AB + r * 528 + kq * 4, &srcB[(size_t)grow * HID + kc * 128 + kq]);
    }
}

__device__ __forceinline__ void chunk_mma(float* acc, uint32_t aA, uint32_t bB)
{
#pragma unroll
    for (int ks = 0; ks < 16; ks++) {
        uint32_t af[4], bf[4];
        ldsm4(af, aA + ks * 32);
        ldsm4(bf, bB + ks * 32);
        mma_tf32(acc + 0, af, bf + 0);
        mma_tf32(acc + 4, af, bf + 2);
    }
}

__global__ void __launch_bounds__(TPB)
lstm_kernel(const int* __restrict__ done,
            const float* __restrict__ c0_in,
            const float* __restrict__ b_ih1,
            const float* __restrict__ b_hh1,
            float* __restrict__ out_hT,
            float* __restrict__ out_cT)
{
    extern __shared__ char sm[];
    float* D_s  = (float*)sm;                        // layer0 D / layer1 D_ih (buf0 A)
    float* D_hh = (float*)(sm + 32 * DS_STR * 4);    // layer1 D_hh

    const int tid  = threadIdx.x;
    const int w    = tid >> 5;
    const int lane = tid & 31;
    const int bq   = blockIdx.x & 3;       // batch quarter
    const int B0   = bq * 32;
    const int u0   = (blockIdx.x >> 2) * NU;
    const int mt   = w >> 1;               // m-tile 0..1
    const int np   = w & 1;                // n-pair 0..1

    const uint32_t sb = smem_u32(sm);
    const int st = lane >> 3;
    const uint32_t aOff = (mt * 16 + (st & 1) * 8 + (lane & 7)) * 528 + (st >> 1) * 16;
    const uint32_t bOff = SM_AB + (np * 16 + (st >> 1) * 8 + (lane & 7)) * 528 + (st & 1) * 16;

    const int bl = tid & 31;               // local batch row
    const int b  = B0 + bl;
    const int ug = (tid >> 5) * 2;         // unit group (2 units per thread)

    float bias1[2][4];
#pragma unroll
    for (int j = 0; j < 2; j++)
#pragma unroll
        for (int g = 0; g < 4; g++) {
            int row = g * HID + u0 + ug + j;
            bias1[j][g] = b_ih1[row] + b_hh1[row];
        }

    float c0r[2], c1r[2];
#pragma unroll
    for (int j = 0; j < 2; j++) {
        c0r[j] = c0_in[(0 * BATCH + b) * HID + u0 + ug + j];
        c1r[j] = c0_in[(1 * BATCH + b) * HID + u0 + ug + j];
    }

    unsigned int phase = 0;

    for (int t = 0; t < T_STEPS; t++) {
        const int p = t & 1;
        const float mk = 1.0f - (float)__ldg(&done[t * BATCH + b]);

        float pre[2][4];
#pragma unroll
        for (int j = 0; j < 2; j++)
#pragma unroll
            for (int g = 0; g < 4; g++)
                pre[j][g] = __ldcg(&g_pre0[((size_t)t * G4H + g * HID + u0 + ug + j) * BATCH + b]);

        __syncthreads();   // prior epilogue D_s reads complete (buf0 reuse)

        // ===== layer 0: D = h0 @ W_hh0^T (mask applied in epilogue) =====
        const float* hA0 = &g_h0[p][0][0];
        float acc[8];
#pragma unroll
        for (int i = 0; i < 8; i++) acc[i] = 0.f;

        stage_async(sb + 0 * SM_BUF, hA0, g_wt0, 0, B0, u0, tid); CP_COMMIT();
        stage_async(sb + 1 * SM_BUF, hA0, g_wt0, 1, B0, u0, tid); CP_COMMIT();
#pragma unroll
        for (int kc = 0; kc < 4; kc++) {
            CP_WAIT1();
            __syncthreads();
            if (kc + 2 < 4) stage_async(sb + ((kc + 2) % 3) * SM_BUF, hA0, g_wt0, kc + 2, B0, u0, tid);
            CP_COMMIT();
            chunk_mma(acc, sb + (kc % 3) * SM_BUF + aOff, sb + (kc % 3) * SM_BUF + bOff);
        }

        __syncthreads();   // all warps past buf0 reads before D_s overlay
        {
            const int r = lane >> 2, c2 = (lane & 3) * 2;
#pragma unroll
            for (int nt = 0; nt < 2; nt++) {
                const int n = np * 16 + nt * 8 + c2;
                D_s[(n + 0) * DS_STR + mt * 16 + r]     = acc[nt * 4 + 0];
                D_s[(n + 1) * DS_STR + mt * 16 + r]     = acc[nt * 4 + 1];
                D_s[(n + 0) * DS_STR + mt * 16 + r + 8] = acc[nt * 4 + 2];
                D_s[(n + 1) * DS_STR + mt * 16 + r + 8] = acc[nt * 4 + 3];
            }
        }
        __syncthreads();
        {
#pragma unroll
            for (int j = 0; j < 2; j++) {
                const int u = ug + j;
                float gi = fmaf(mk, D_s[(0 * 8 + u) * DS_STR + bl], pre[j][0]);
                float gf = fmaf(mk, D_s[(1 * 8 + u) * DS_STR + bl], pre[j][1]);
                float gg = fmaf(mk, D_s[(2 * 8 + u) * DS_STR + bl], pre[j][2]);
                float go = fmaf(mk, D_s[(3 * 8 + u) * DS_STR + bl], pre[j][3]);
                float c  = fmaf(sigmoidf_(gf), c0r[j] * mk, sigmoidf_(gi) * tanhf(gg));
                c0r[j]   = c;
                g_h0[p ^ 1][b][u0 + u] = tf32r(sigmoidf_(go) * tanhf(c));
            }
        }

        grid_bar(++phase);

        // ===== layer 1: D_ih = h0_new @ W_ih1^T ; D_hh = h1 @ W_hh1^T =====
        const float* hA1i = &g_h0[p ^ 1][0][0];
        const float* hA1h = &g_h1[p][0][0];
        float accI[8], accH[8];
#pragma unroll
        for (int i = 0; i < 8; i++) { accI[i] = 0.f; accH[i] = 0.f; }

        stage_async(sb + 0 * SM_BUF, hA1i, g_wt1i, 0, B0, u0, tid); CP_COMMIT();
        stage_async(sb + 1 * SM_BUF, hA1i, g_wt1i, 1, B0, u0, tid); CP_COMMIT();
#pragma unroll
        for (int kc = 0; kc < 8; kc++) {
            CP_WAIT1();
            __syncthreads();
            if (kc + 2 < 8) {
                const int kcc = kc + 2;
                stage_async(sb + (kcc % 3) * SM_BUF,
                            (kcc < 4) ? hA1i : hA1h,
                            (kcc < 4) ? g_wt1i : g_wt1h,
                            kcc & 3, B0, u0, tid);
            }
            CP_COMMIT();
            chunk_mma((kc < 4) ? accI : accH,
                      sb + (kc % 3) * SM_BUF + aOff, sb + (kc % 3) * SM_BUF + bOff);
        }

        __syncthreads();   // safe overlay of buf0 by D_ih/D_hh
        {
            const int r = lane >> 2, c2 = (lane & 3) * 2;
#pragma unroll
            for (int nt = 0; nt < 2; nt++) {
                const int n = np * 16 + nt * 8 + c2;
                D_s [(n + 0) * DS_STR + mt * 16 + r]     = accI[nt * 4 + 0];
                D_s [(n + 1) * DS_STR + mt * 16 + r]     = accI[nt * 4 + 1];
                D_s [(n + 0) * DS_STR + mt * 16 + r + 8] = accI[nt * 4 + 2];
                D_s [(n + 1) * DS_STR + mt * 16 + r + 8] = accI[nt * 4 + 3];
                D_hh[(n + 0) * DS_STR + mt * 16 + r]     = accH[nt * 4 + 0];
                D_hh[(n + 1) * DS_STR + mt * 16 + r]     = accH[nt * 4 + 1];
                D_hh[(n + 0) * DS_STR + mt * 16 + r + 8] = accH[nt * 4 + 2];
                D_hh[(n + 1) * DS_STR + mt * 16 + r + 8] = accH[nt * 4 + 3];
            }
        }
        __syncthreads();
        {
#pragma unroll
            for (int j = 0; j < 2; j++) {
                const int u = ug + j;
                float gi = D_s[(0 * 8 + u) * DS_STR + bl] + fmaf(mk, D_hh[(0 * 8 + u) * DS_STR + bl], bias1[j][0]);
                float gf = D_s[(1 * 8 + u) * DS_STR + bl] + fmaf(mk, D_hh[(1 * 8 + u) * DS_STR + bl], bias1[j][1]);
                float gg = D_s[(2 * 8 + u) * DS_STR + bl] + fmaf(mk, D_hh[(2 * 8 + u) * DS_STR + bl], bias1[j][2]);
                float go = D_s[(3 * 8 + u) * DS_STR + bl] + fmaf(mk, D_hh[(3 * 8 + u) * DS_STR + bl], bias1[j][3]);
                float c  = fmaf(sigmoidf_(gf), c1r[j] * mk, sigmoidf_(gi) * tanhf(gg));
                c1r[j]   = c;
                float h  = tf32r(sigmoidf_(go) * tanhf(c));
                g_h1[p ^ 1][b][u0 + u] = h;
                g_hidden[((size_t)t * BATCH + b) * HID + u0 + u] = h;
            }
        }
        // next step's top sync + grid_bar order everything else
    }

    grid_bar(++phase);

#pragma unroll
    for (int j = 0; j < 2; j++) {
        out_cT[(0 * BATCH + b) * HID + u0 + ug + j] = c0r[j];
        out_cT[(1 * BATCH + b) * HID + u0 + ug + j] = c1r[j];
    }
    for (int i = blockIdx.x * TPB + tid; i < BATCH * HID; i += NCTA * TPB) {
        out_hT[i]               = __ldcg(&(&g_h0[0][0][0])[i]);
        out_hT[BATCH * HID + i] = __ldcg(&(&g_h1[0][0][0])[i]);
    }
}

// ---------------- actor/critic heads -----------------------------------------
__global__ void __launch_bounds__(256)
head_kernel(const float* __restrict__ Wa, const float* __restrict__ ba,
            const float* __restrict__ Wc, const float* __restrict__ bc,
            float* __restrict__ out)
{
    __shared__ float Ws[NACT * HID];
    __shared__ float bs[NACT];
    for (int i = threadIdx.x; i < 18 * HID; i += blockDim.x) Ws[i] = Wa[i];
    for (int i = threadIdx.x; i < HID; i += blockDim.x) Ws[18 * HID + i] = Wc[i];
    if (threadIdx.x < 18) bs[threadIdx.x] = ba[threadIdx.x];
    if (threadIdx.x == 18) bs[18] = bc[0];
    __syncthreads();

    const int warp = threadIdx.x >> 5;
    const int lane = threadIdx.x & 31;
    const size_t m = (size_t)blockIdx.x * 8 + warp;

    const float* hrow = &g_hidden[m * HID];
    float hv[16];
#pragma unroll
    for (int j = 0; j < 16; j++) hv[j] = hrow[lane + j * 32];

#pragma unroll
    for (int a = 0; a < NACT; a++) {
        float s = 0.f;
#pragma unroll
        for (int j = 0; j < 16; j++) s = fmaf(hv[j], Ws[a * HID + lane + j * 32], s);
#pragma unroll
        for (int off = 16; off > 0; off >>= 1) s += __shfl_xor_sync(0xffffffffu, s, off);
        if (lane == a) out[m * NACT + a] = s + bs[a];
    }
}

// ---------------- launch ------------------------------------------------------
extern "C" void kernel_launch(void* const* d_in, const int* in_sizes, int n_in,
                              void* d_out, int out_size)
{
    (void)in_sizes; (void)n_in; (void)out_size;
    const float* x     = (const float*)d_in[0];
    const int*   done  = (const int*)  d_in[1];
    const float* h0    = (const float*)d_in[2];
    const float* c0    = (const float*)d_in[3];
    const float* W_ih0 = (const float*)d_in[4];
    const float* W_hh0 = (const float*)d_in[5];
    const float* b_ih0 = (const float*)d_in[6];
    const float* b_hh0 = (const float*)d_in[7];
    const float* W_ih1 = (const float*)d_in[8];
    const float* W_hh1 = (const float*)d_in[9];
    const float* b_ih1 = (const float*)d_in[10];
    const float* b_hh1 = (const float*)d_in[11];
    const float* W_a   = (const float*)d_in[12];
    const float* b_a   = (const float*)d_in[13];
    const float* W_c   = (const float*)d_in[14];
    const float* b_c   = (const float*)d_in[15];

    float* out    = (float*)d_out;
    float* out_hT = out + (size_t)T_STEPS * BATCH * NACT;
    float* out_cT = out_hT + 2 * BATCH * HID;

    cudaFuncSetAttribute(lstm_kernel, cudaFuncAttributeMaxDynamicSharedMemorySize, SM_TOTAL);
    cudaFuncSetAttribute(pre_mma_kernel, cudaFuncAttributeMaxDynamicSharedMemorySize, PM_TOTAL);

    init_kernel<<<64, 256>>>(h0);
    wt_kernel<<<132, 256>>>(W_hh0, W_ih1, W_hh1);

    dim3 gg(G4H / 128, (T_STEPS * BATCH) / 64);
    pre_mma_kernel<<<gg, 256, PM_TOTAL>>>(x, W_ih0, b_ih0, b_hh0);

    lstm_kernel<<<NCTA, TPB, SM_TOTAL>>>(done, c0, b_ih1, b_hh1, out_hT, out_cT);

    head_kernel<<<(T_STEPS * BATCH) / 8, 256>>>(W_a, b_a, W_c, b_c, out);
}

// round 16
// speedup vs baseline: 1.0459x; 1.0459x over previous
#include <cuda_runtime.h>
#include <math.h>
#include <cstdint>

#define T_STEPS 512
#define BATCH   128
#define IN_DIM  544
#define HID     512
#define G4H     2048
#define NACT    19
#define NCTA    128     // CTA = (batch-half, unit-group of 8)
#define TPB     256     // 8 warps: warp = (m-tile 0..3, n-pair 0..1)
#define NU      8       // units per CTA (32 gate rows)

// LSTM SMEM: three (A 64x132 + B 32x132) circular buffers
#define SM_AB    33792                        // B offset inside a buffer
#define SM_BUF   50688                        // buffer stride
#define SM_TOTAL (3 * SM_BUF)                 // 152064

// pre-GEMM (mma) SMEM
#define PM_STR   140
#define PM_A     0
#define PM_B     (64 * PM_STR * 4)
#define PM_BIAS  (PM_B + 128 * PM_STR * 4)
#define PM_TOTAL (PM_BIAS + 512)

// ---------------- scratch ----------------------------------------------------
__device__ float g_pre0[(size_t)T_STEPS * G4H * BATCH];     // [t][n][b]
__device__ float g_hidden[(size_t)T_STEPS * BATCH * HID];
__device__ float g_h0[2][BATCH][HID];                       // tf32-rounded h
__device__ float g_h1[2][BATCH][HID];
__device__ float g_wt0[G4H * HID];                          // tf32-rounded weights
__device__ float g_wt1i[G4H * HID];
__device__ float g_wt1h[G4H * HID];
__device__ unsigned int g_bar_count;
__device__ unsigned int g_bar_release;

// ---------------- helpers ----------------------------------------------------
__device__ __forceinline__ uint32_t smem_u32(const void* p) {
    uint32_t a;
    asm("{ .reg .u64 t; cvta.to.shared.u64 t, %1; cvt.u32.u64 %0, t; }" : "=r"(a) : "l"(p));
    return a;
}
__device__ __forceinline__ float tf32r(float x) {
    uint32_t o; asm("cvt.rna.tf32.f32 %0, %1;" : "=r"(o) : "f"(x));
    return __uint_as_float(o);
}
__device__ __forceinline__ void ldsm4(uint32_t* r, uint32_t addr) {
    asm volatile("ldmatrix.sync.aligned.m8n8.x4.shared.b16 {%0,%1,%2,%3}, [%4];"
                 : "=r"(r[0]), "=r"(r[1]), "=r"(r[2]), "=r"(r[3]) : "r"(addr));
}
__device__ __forceinline__ void mma_tf32(float* d, const uint32_t* a, const uint32_t* b) {
    asm volatile("mma.sync.aligned.m16n8k8.row.col.f32.tf32.tf32.f32 "
                 "{%0,%1,%2,%3}, {%4,%5,%6,%7}, {%8,%9}, {%0,%1,%2,%3};"
                 : "+f"(d[0]), "+f"(d[1]), "+f"(d[2]), "+f"(d[3])
                 : "r"(a[0]), "r"(a[1]), "r"(a[2]), "r"(a[3]), "r"(b[0]), "r"(b[1]));
}
__device__ __forceinline__ void cp16cg(uint32_t d, const void* s) {
    asm volatile("cp.async.cg.shared.global [%0], [%1], 16;" :: "r"(d), "l"(s));
}
__device__ __forceinline__ void cp16ca(uint32_t d, const void* s) {
    asm volatile("cp.async.ca.shared.global [%0], [%1], 16;" :: "r"(d), "l"(s));
}
#define CP_COMMIT() asm volatile("cp.async.commit_group;" ::: "memory")
#define CP_WAIT0()  asm volatile("cp.async.wait_group 0;" ::: "memory")
#define CP_WAIT1()  asm volatile("cp.async.wait_group 1;" ::: "memory")
#define CP_WAIT2()  asm volatile("cp.async.wait_group 2;" ::: "memory")

// fast activations (saturating, __expf-based; rel err ~1e-6)
__device__ __forceinline__ float sigmoidf_(float x) {
    return __fdividef(1.f, 1.f + __expf(-x));
}
__device__ __forceinline__ float tanhf_(float x) {
    float t = __expf(2.f * x);
    return 1.f - __fdividef(2.f, t + 1.f);
}

// ---------------- init / weight-round kernels --------------------------------
__global__ void init_kernel(const float* __restrict__ h0) {
    if (blockIdx.x == 0 && threadIdx.x == 0) { g_bar_count = 0u; g_bar_release = 0u; }
    const int n = BATCH * HID;
    for (int i = blockIdx.x * blockDim.x + threadIdx.x; i < n; i += gridDim.x * blockDim.x) {
        (&g_h0[0][0][0])[i] = tf32r(h0[i]);
        (&g_h1[0][0][0])[i] = tf32r(h0[n + i]);
    }
}

__global__ void wt_kernel(const float* __restrict__ W0, const float* __restrict__ W1i,
                          const float* __restrict__ W1h) {
    const int n = G4H * HID;
    for (int i = blockIdx.x * blockDim.x + threadIdx.x; i < n; i += gridDim.x * blockDim.x) {
        g_wt0[i]  = tf32r(W0[i]);
        g_wt1i[i] = tf32r(W1i[i]);
        g_wt1h[i] = tf32r(W1h[i]);
    }
}

// ---------------- pre-GEMM via tf32 mma (unchanged) ---------------------------
__global__ void __launch_bounds__(256)
pre_mma_kernel(const float* __restrict__ X, const float* __restrict__ W,
               const float* __restrict__ bA, const float* __restrict__ bB)
{
    extern __shared__ char sm[];
    float* bias = (float*)(sm + PM_BIAS);
    float* D_s  = (float*)sm;

    const int tid  = threadIdx.x;
    const int w    = tid >> 5;
    const int lane = tid & 31;
    const int n0   = blockIdx.x * 128;
    const int row0 = blockIdx.y * 64;
    const int tt   = blockIdx.y >> 1;
    const int b0   = (blockIdx.y & 1) * 64;
    const int mt   = w >> 1;
    const int nh   = w & 1;

    if (tid < 128) bias[tid] = bA[n0 + tid] + bB[n0 + tid];

    const uint32_t sb = smem_u32(sm);
    const int st = lane >> 3;
    const uint32_t aA = sb + PM_A + (mt * 16 + (st & 1) * 8 + (lane & 7)) * 560 + (st >> 1) * 16;
    const uint32_t bBq = sb + PM_B + (nh * 64 + (st >> 1) * 8 + (lane & 7)) * 560 + (st & 1) * 16;

    float acc[32];
#pragma unroll
    for (int i = 0; i < 32; i++) acc[i] = 0.f;

    for (int kc = 0; kc < 4; kc++) {
        __syncthreads();
        {
            const int r = tid >> 2, q = tid & 3;
#pragma unroll
            for (int j = 0; j < 9; j++) {
                int c4 = j * 4 + q;
                if (c4 < 34) {
                    float4 v = __ldg((const float4*)&X[(size_t)(row0 + r) * IN_DIM + kc * 136 + c4 * 4]);
                    v.x = tf32r(v.x); v.y = tf32r(v.y); v.z = tf32r(v.z); v.w = tf32r(v.w);
                    *(float4*)(sm + PM_A + r * 560 + c4 * 16) = v;
                }
            }
        }
        {
            const int r = tid >> 1, q = tid & 1;
#pragma unroll
            for (int j = 0; j < 17; j++) {
                int c4 = j * 2 + q;
                float4 v = __ldg((const float4*)&W[(size_t)(n0 + r) * IN_DIM + kc * 136 + c4 * 4]);
                v.x = tf32r(v.x); v.y = tf32r(v.y); v.z = tf32r(v.z); v.w = tf32r(v.w);
                *(float4*)(sm + PM_B + r * 560 + c4 * 16) = v;
            }
        }
        __syncthreads();
#pragma unroll
        for (int ks = 0; ks < 17; ks++) {
            uint32_t af[4];
            ldsm4(af, aA + ks * 32);
#pragma unroll
            for (int nb = 0; nb < 4; nb++) {
                uint32_t bf[4];
                ldsm4(bf, bBq + nb * 16 * 560 + ks * 32);
                mma_tf32(acc + nb * 8 + 0, af, bf + 0);
                mma_tf32(acc + nb * 8 + 4, af, bf + 2);
            }
        }
    }

    __syncthreads();
    {
        const int r = lane >> 2, c2 = (lane & 3) * 2;
#pragma unroll
        for (int nb = 0; nb < 4; nb++) {
            const int nbase = nh * 64 + nb * 16;
            D_s[(nbase + c2 + 0) * 68 + mt * 16 + r]     = acc[nb * 8 + 0];
            D_s[(nbase + c2 + 1) * 68 + mt * 16 + r]     = acc[nb * 8 + 1];
            D_s[(nbase + c2 + 0) * 68 + mt * 16 + r + 8] = acc[nb * 8 + 2];
            D_s[(nbase + c2 + 1) * 68 + mt * 16 + r + 8] = acc[nb * 8 + 3];
            D_s[(nbase + 8 + c2 + 0) * 68 + mt * 16 + r]     = acc[nb * 8 + 4];
            D_s[(nbase + 8 + c2 + 1) * 68 + mt * 16 + r]     = acc[nb * 8 + 5];
            D_s[(nbase + 8 + c2 + 0) * 68 + mt * 16 + r + 8] = acc[nb * 8 + 6];
            D_s[(nbase + 8 + c2 + 1) * 68 + mt * 16 + r + 8] = acc[nb * 8 + 7];
        }
    }
    __syncthreads();
    {
        const int n = tid >> 1, mh = tid & 1;
        const float bs = bias[n];
        float* dst = &g_pre0[((size_t)tt * G4H + n0 + n) * BATCH + b0 + mh * 32];
        const float* src = &D_s[n * 68 + mh * 32];
#pragma unroll
        for (int s = 0; s < 8; s++) {
            float4 v = ((const float4*)src)[s];
            ((float4*)dst)[s] = make_float4(v.x + bs, v.y + bs, v.z + bs, v.w + bs);
        }
    }
}

// ---------------- persistent tensor (mma.sync + cp.async) LSTM ----------------
__device__ __forceinline__ void grid_bar(unsigned int phase) {
    __threadfence();
    __syncthreads();
    if (threadIdx.x == 0) {
        unsigned int arrived = atomicAdd(&g_bar_count, 1u) + 1u;
        if (arrived == (unsigned)NCTA * phase) {
            atomicExch(&g_bar_release, phase);
        } else {
            while (*(volatile unsigned int*)&g_bar_release < phase) { __nanosleep(64); }
        }
    }
    __syncthreads();
}

// stage one chunk into buffer: A 64 rows (batch half), B 32 gate rows
__device__ __forceinline__ void stage_async(uint32_t sbuf,
                                            const float* __restrict__ srcA,
                                            const float* __restrict__ srcB,
                                            int kc, int B0, int u0, int tid)
{
#pragma unroll
    for (int it = 0; it < 8; it++) {
        const int idx = it * TPB + tid;
        const int m  = idx >> 5;
        const int kq = (idx & 31) << 2;
        cp16cg(sbuf + m * 528 + kq * 4, &srcA[(B0 + m) * HID + kc * 128 + kq]);
    }
#pragma unroll
    for (int it = 0; it < 4; it++) {
        const int idx = it * TPB + tid;
        const int r  = idx >> 5;
        const int kq = (idx & 31) << 2;
        const int grow = (r >> 3) * HID + u0 + (r & 7);
        cp16ca(sbuf + SM_AB + r * 528 + kq * 4, &srcB[(size_t)grow * HID + kc * 128 + kq]);
    }
}

__device__ __forceinline__ void chunk_mma(float* acc, uint32_t aA, uint32_t bB)
{
#pragma unroll
    for (int ks = 0; ks < 16; ks++) {
        uint32_t af[4], bf[4];
        ldsm4(af, aA + ks * 32);
        ldsm4(bf, bB + ks * 32);
        mma_tf32(acc + 0, af, bf + 0);
        mma_tf32(acc + 4, af, bf + 2);
    }
}

__global__ void __launch_bounds__(TPB, 1)
lstm_kernel(const int* __restrict__ done,
            const float* __restrict__ c0_in,
            const float* __restrict__ b_ih1,
            const float* __restrict__ b_hh1,
            float* __restrict__ out_hT,
            float* __restrict__ out_cT)
{
    extern __shared__ char sm[];
    float* D_s  = (float*)sm;              // layer0 D / layer1 D_ih (overlays buf0 A)
    float* D_hh = (float*)(sm + 16896);    // layer1 D_hh (second half of buf0 A)

    const int tid  = threadIdx.x;
    const int w    = tid >> 5;
    const int lane = tid & 31;
    const int bh   = blockIdx.x & 1;
    const int B0   = bh * 64;
    const int u0   = (blockIdx.x >> 1) * NU;
    const int mt   = w >> 1;
    const int np   = w & 1;

    const uint32_t sb = smem_u32(sm);
    const int st = lane >> 3;
    const uint32_t aOff = (mt * 16 + (st & 1) * 8 + (lane & 7)) * 528 + (st >> 1) * 16;
    const uint32_t bOff = SM_AB + (np * 16 + (st >> 1) * 8 + (lane & 7)) * 528 + (st & 1) * 16;

    const int bl = tid & 63;
    const int b  = B0 + bl;
    const int ug = (tid >> 6) * 2;

    float bias1[2][4];
#pragma unroll
    for (int j = 0; j < 2; j++)
#pragma unroll
        for (int g = 0; g < 4; g++) {
            int row = g * HID + u0 + ug + j;
            bias1[j][g] = b_ih1[row] + b_hh1[row];
        }

    float c0r[2], c1r[2];
#pragma unroll
    for (int j = 0; j < 2; j++) {
        c0r[j] = c0_in[(0 * BATCH + b) * HID + u0 + ug + j];
        c1r[j] = c0_in[(1 * BATCH + b) * HID + u0 + ug + j];
    }

    unsigned int phase = 0;

    // bootstrap: stage layer0 chunks 0,1 of step 0 into bufs 1,2
    stage_async(sb + 1 * SM_BUF, &g_h0[0][0][0], g_wt0, 0, B0, u0, tid); CP_COMMIT();
    stage_async(sb + 2 * SM_BUF, &g_h0[0][0][0], g_wt0, 1, B0, u0, tid); CP_COMMIT();

    for (int t = 0; t < T_STEPS; t++) {
        const int p = t & 1;
        const float mk = 1.0f - (float)__ldg(&done[t * BATCH + b]);

        float pre[2][4];
#pragma unroll
        for (int j = 0; j < 2; j++)
#pragma unroll
            for (int g = 0; g < 4; g++)
                pre[j][g] = __ldcg(&g_pre0[((size_t)t * G4H + g * HID + u0 + ug + j) * BATCH + b]);

        __syncthreads();   // prior epilogue D_s (buf0) reads complete

        // ===== layer 0: D = h0 @ W_hh0^T  (chunks: c0->buf1, c1->buf2, c2->buf0, c3->buf1) =====
        const float* hA0 = &g_h0[p][0][0];
        float acc[8];
#pragma unroll
        for (int i = 0; i < 8; i++) acc[i] = 0.f;

        stage_async(sb + 0 * SM_BUF, hA0, g_wt0, 2, B0, u0, tid); CP_COMMIT();   // c2 (buf0 free now)

        CP_WAIT2(); __syncthreads();                                              // c0 ready
        chunk_mma(acc, sb + 1 * SM_BUF + aOff, sb + 1 * SM_BUF + bOff);

        CP_WAIT1(); __syncthreads();                                              // c1 ready; buf1 free
        stage_async(sb + 1 * SM_BUF, hA0, g_wt0, 3, B0, u0, tid); CP_COMMIT();    // c3 -> buf1
        chunk_mma(acc, sb + 2 * SM_BUF + aOff, sb + 2 * SM_BUF + bOff);

        CP_WAIT1(); __syncthreads();                                              // c2 ready
        chunk_mma(acc, sb + 0 * SM_BUF + aOff, sb + 0 * SM_BUF + bOff);

        CP_WAIT0(); __syncthreads();                                              // c3 ready
        chunk_mma(acc, sb + 1 * SM_BUF + aOff, sb + 1 * SM_BUF + bOff);

        __syncthreads();   // all warps past buf reads before D_s overlay
        {
            const int r = lane >> 2, c2 = (lane & 3) * 2;
#pragma unroll
            for (int nt = 0; nt < 2; nt++) {
                const int n = np * 16 + nt * 8 + c2;
                D_s[(n + 0) * 132 + mt * 16 + r]     = acc[nt * 4 + 0];
                D_s[(n + 1) * 132 + mt * 16 + r]     = acc[nt * 4 + 1];
                D_s[(n + 0) * 132 + mt * 16 + r + 8] = acc[nt * 4 + 2];
                D_s[(n + 1) * 132 + mt * 16 + r + 8] = acc[nt * 4 + 3];
            }
        }
        __syncthreads();
        {
#pragma unroll
            for (int j = 0; j < 2; j++) {
                const int u = ug + j;
                float gi = fmaf(mk, D_s[(0 * 8 + u) * 132 + bl], pre[j][0]);
                float gf = fmaf(mk, D_s[(1 * 8 + u) * 132 + bl], pre[j][1]);
                float gg = fmaf(mk, D_s[(2 * 8 + u) * 132 + bl], pre[j][2]);
                float go = fmaf(mk, D_s[(3 * 8 + u) * 132 + bl], pre[j][3]);
                float c  = fmaf(sigmoidf_(gf), c0r[j] * mk, sigmoidf_(gi) * tanhf_(gg));
                c0r[j]   = c;
                g_h0[p ^ 1][b][u0 + u] = tf32r(sigmoidf_(go) * tanhf_(c));
            }
        }

        grid_bar(++phase);

        // ===== layer 1: D_ih = h0_new @ W_ih1^T ; D_hh = h1 @ W_hh1^T =====
        const float* hA1i = &g_h0[p ^ 1][0][0];
        const float* hA1h = &g_h1[p][0][0];
        float accI[8], accH[8];
#pragma unroll
        for (int i = 0; i < 8; i++) { accI[i] = 0.f; accH[i] = 0.f; }

        stage_async(sb + 0 * SM_BUF, hA1i, g_wt1i, 0, B0, u0, tid); CP_COMMIT();
        stage_async(sb + 1 * SM_BUF, hA1i, g_wt1i, 1, B0, u0, tid); CP_COMMIT();
#pragma unroll
        for (int kc = 0; kc < 8; kc++) {
            CP_WAIT1();
            __syncthreads();
            if (kc + 2 < 8) {
                const int kcc = kc + 2;
                stage_async(sb + (kcc % 3) * SM_BUF,
                            (kcc < 4) ? hA1i : hA1h,
                            (kcc < 4) ? g_wt1i : g_wt1h,
                            kcc & 3, B0, u0, tid);
            }
            CP_COMMIT();
            chunk_mma((kc < 4) ? accI : accH,
                      sb + (kc % 3) * SM_BUF + aOff, sb + (kc % 3) * SM_BUF + bOff);
        }

        __syncthreads();   // all layer1 buf reads done (buf1 last read at c7)

        // cross-step prefetch: stage layer0 chunks 0,1 of step t+1 into bufs 1,2.
        // Safe: h0_new complete globally (we are post-grid_bar(t)); bufs 1,2 free.
        if (t + 1 < T_STEPS) {
            const float* hN = &g_h0[p ^ 1][0][0];
            stage_async(sb + 1 * SM_BUF, hN, g_wt0, 0, B0, u0, tid); CP_COMMIT();
            stage_async(sb + 2 * SM_BUF, hN, g_wt0, 1, B0, u0, tid); CP_COMMIT();
        }

        {
            const int r = lane >> 2, c2 = (lane & 3) * 2;
#pragma unroll
            for (int nt = 0; nt < 2; nt++) {
                const int n = np * 16 + nt * 8 + c2;
                D_s [(n + 0) * 132 + mt * 16 + r]     = accI[nt * 4 + 0];
                D_s [(n + 1) * 132 + mt * 16 + r]     = accI[nt * 4 + 1];
                D_s [(n + 0) * 132 + mt * 16 + r + 8] = accI[nt * 4 + 2];
                D_s [(n + 1) * 132 + mt * 16 + r + 8] = accI[nt * 4 + 3];
                D_hh[(n + 0) * 132 + mt * 16 + r]     = accH[nt * 4 + 0];
                D_hh[(n + 1) * 132 + mt * 16 + r]     = accH[nt * 4 + 1];
                D_hh[(n + 0) * 132 + mt * 16 + r + 8] = accH[nt * 4 + 2];
                D_hh[(n + 1) * 132 + mt * 16 + r + 8] = accH[nt * 4 + 3];
            }
        }
        __syncthreads();
        {
#pragma unroll
            for (int j = 0; j < 2; j++) {
                const int u = ug + j;
                float gi = D_s[(0 * 8 + u) * 132 + bl] + fmaf(mk, D_hh[(0 * 8 + u) * 132 + bl], bias1[j][0]);
                float gf = D_s[(1 * 8 + u) * 132 + bl] + fmaf(mk, D_hh[(1 * 8 + u) * 132 + bl], bias1[j][1]);
                float gg = D_s[(2 * 8 + u) * 132 + bl] + fmaf(mk, D_hh[(2 * 8 + u) * 132 + bl], bias1[j][2]);
                float go = D_s[(3 * 8 + u) * 132 + bl] + fmaf(mk, D_hh[(3 * 8 + u) * 132 + bl], bias1[j][3]);
                float c  = fmaf(sigmoidf_(gf), c1r[j] * mk, sigmoidf_(gi) * tanhf_(gg));
                c1r[j]   = c;
                float h  = tf32r(sigmoidf_(go) * tanhf_(c));
                g_h1[p ^ 1][b][u0 + u] = h;
                g_hidden[((size_t)t * BATCH + b) * HID + u0 + u] = h;
            }
        }
        // next step's top sync + grid_bar order everything else
    }

    grid_bar(++phase);

#pragma unroll
    for (int j = 0; j < 2; j++) {
        out_cT[(0 * BATCH + b) * HID + u0 + ug + j] = c0r[j];
        out_cT[(1 * BATCH + b) * HID + u0 + ug + j] = c1r[j];
    }
    for (int i = blockIdx.x * TPB + tid; i < BATCH * HID; i += NCTA * TPB) {
        out_hT[i]               = __ldcg(&(&g_h0[0][0][0])[i]);
        out_hT[BATCH * HID + i] = __ldcg(&(&g_h1[0][0][0])[i]);
    }
}

// ---------------- actor/critic heads -----------------------------------------
__global__ void __launch_bounds__(256)
head_kernel(const float* __restrict__ Wa, const float* __restrict__ ba,
            const float* __restrict__ Wc, const float* __restrict__ bc,
            float* __restrict__ out)
{
    __shared__ float Ws[NACT * HID];
    __shared__ float bs[NACT];
    for (int i = threadIdx.x; i < 18 * HID; i += blockDim.x) Ws[i] = Wa[i];
    for (int i = threadIdx.x; i < HID; i += blockDim.x) Ws[18 * HID + i] = Wc[i];
    if (threadIdx.x < 18) bs[threadIdx.x] = ba[threadIdx.x];
    if (threadIdx.x == 18) bs[18] = bc[0];
    __syncthreads();

    const int warp = threadIdx.x >> 5;
    const int lane = threadIdx.x & 31;
    const size_t m = (size_t)blockIdx.x * 8 + warp;

    const float* hrow = &g_hidden[m * HID];
    float hv[16];
#pragma unroll
    for (int j = 0; j < 16; j++) hv[j] = hrow[lane + j * 32];

#pragma unroll
    for (int a = 0; a < NACT; a++) {
        float s = 0.f;
#pragma unroll
        for (int j = 0; j < 16; j++) s = fmaf(hv[j], Ws[a * HID + lane + j * 32], s);
#pragma unroll
        for (int off = 16; off > 0; off >>= 1) s += __shfl_xor_sync(0xffffffffu, s, off);
        if (lane == a) out[m * NACT + a] = s + bs[a];
    }
}

// ---------------- launch ------------------------------------------------------
extern "C" void kernel_launch(void* const* d_in, const int* in_sizes, int n_in,
                              void* d_out, int out_size)
{
    (void)in_sizes; (void)n_in; (void)out_size;
    const float* x     = (const float*)d_in[0];
    const int*   done  = (const int*)  d_in[1];
    const float* h0    = (const float*)d_in[2];
    const float* c0    = (const float*)d_in[3];
    const float* W_ih0 = (const float*)d_in[4];
    const float* W_hh0 = (const float*)d_in[5];
    const float* b_ih0 = (const float*)d_in[6];
    const float* b_hh0 = (const float*)d_in[7];
    const float* W_ih1 = (const float*)d_in[8];
    const float* W_hh1 = (const float*)d_in[9];
    const float* b_ih1 = (const float*)d_in[10];
    const float* b_hh1 = (const float*)d_in[11];
    const float* W_a   = (const float*)d_in[12];
    const float* b_a   = (const float*)d_in[13];
    const float* W_c   = (const float*)d_in[14];
    const float* b_c   = (const float*)d_in[15];

    float* out    = (float*)d_out;
    float* out_hT = out + (size_t)T_STEPS * BATCH * NACT;
    float* out_cT = out_hT + 2 * BATCH * HID;

    cudaFuncSetAttribute(lstm_kernel, cudaFuncAttributeMaxDynamicSharedMemorySize, SM_TOTAL);
    cudaFuncSetAttribute(pre_mma_kernel, cudaFuncAttributeMaxDynamicSharedMemorySize, PM_TOTAL);

    init_kernel<<<64, 256>>>(h0);
    wt_kernel<<<132, 256>>>(W_hh0, W_ih1, W_hh1);

    dim3 gg(G4H / 128, (T_STEPS * BATCH) / 64);
    pre_mma_kernel<<<gg, 256, PM_TOTAL>>>(x, W_ih0, b_ih0, b_hh0);

    lstm_kernel<<<NCTA, TPB, SM_TOTAL>>>(done, c0, b_ih1, b_hh1, out_hT, out_cT);

    head_kernel<<<(T_STEPS * BATCH) / 8, 256>>>(W_a, b_a, W_c, b_c, out);
}